// round 14
// baseline (speedup 1.0000x reference)
#include <cuda_runtime.h>
#include <cuda_fp16.h>
#include <math.h>

#define NN 100000
#define EE 1600000
#define HH 128
#define CC 40
#define NBLK 196        // ceil(100000/512)
#define GFULL 782       // ceil(100000/128)
#define NB_E 6250       // ceil(EE/256)

// ---------------- scratch (no allocations allowed) ----------------
__device__ __half g_hpre16[NN * HH];   // fp16 h-pre (gemm16 input / self-term)
__device__ char   g_hq8[NN * HH];      // int8 h-pre (agg gathers)
__device__ float  g_hscl[NN];          // per-row dequant scale
__device__ __half g_h116[NN * HH];
__device__ __half g_h216[NN * HH];
__device__ float  g_dinv[NN];
__device__ int    g_deg[NN];           // invariant: zero at launch entry
__device__ int    g_rowptr[NN + 1];
__device__ int    g_cursor[NN];
__device__ int2   g_epack[EE];         // (src, __float_as_int(coef))
__device__ int    g_bsum[NBLK];

// ---------------- f32x2 helpers ----------------
__device__ __forceinline__ unsigned long long fma2(unsigned long long a,
                                                   unsigned long long b,
                                                   unsigned long long c) {
    unsigned long long d;
    asm("fma.rn.f32x2 %0, %1, %2, %3;" : "=l"(d) : "l"(a), "l"(b), "l"(c));
    return d;
}
__device__ __forceinline__ unsigned long long pk2(float lo, float hi) {
    unsigned long long d;
    asm("mov.b64 %0, {%1, %2};" : "=l"(d) : "f"(lo), "f"(hi));
    return d;
}
__device__ __forceinline__ float2 upk(unsigned long long v) {
    float2 r;
    asm("mov.b64 {%0, %1}, %2;" : "=f"(r.x), "=f"(r.y) : "l"(v));
    return r;
}

// ---------------- HMMA helpers ----------------
__device__ __forceinline__ void ldsm_x4(unsigned& r0, unsigned& r1, unsigned& r2, unsigned& r3,
                                        const void* p) {
    unsigned addr = (unsigned)__cvta_generic_to_shared(p);
    asm volatile("ldmatrix.sync.aligned.m8n8.x4.shared.b16 {%0,%1,%2,%3}, [%4];"
                 : "=r"(r0), "=r"(r1), "=r"(r2), "=r"(r3) : "r"(addr));
}
__device__ __forceinline__ void ldsm_x4_t(unsigned& r0, unsigned& r1, unsigned& r2, unsigned& r3,
                                          const void* p) {
    unsigned addr = (unsigned)__cvta_generic_to_shared(p);
    asm volatile("ldmatrix.sync.aligned.m8n8.x4.trans.shared.b16 {%0,%1,%2,%3}, [%4];"
                 : "=r"(r0), "=r"(r1), "=r"(r2), "=r"(r3) : "r"(addr));
}
__device__ __forceinline__ void mma16816(float* d, const unsigned* a, unsigned b0, unsigned b1) {
    asm volatile("mma.sync.aligned.m16n8k16.row.col.f32.f16.f16.f32 "
                 "{%0,%1,%2,%3}, {%4,%5,%6,%7}, {%8,%9}, {%0,%1,%2,%3};"
                 : "+f"(d[0]), "+f"(d[1]), "+f"(d[2]), "+f"(d[3])
                 : "r"(a[0]), "r"(a[1]), "r"(a[2]), "r"(a[3]), "r"(b0), "r"(b1));
}

// ---------------- HMMA gemm body: fp16 out + int8/scale shadow ----------------
struct HSmem { __half a[128][72]; __half w[64][136]; float rmax[128]; };

template <bool F16IN>
__device__ __forceinline__ void gemm_hmma_body(HSmem& sm,
                                               const void* __restrict__ Ap,
                                               const float* __restrict__ W,
                                               __half* __restrict__ C16,
                                               char* __restrict__ Q8,
                                               float* __restrict__ SCL,
                                               int row0, int t) {
    const int lane = t & 31, wid = t >> 5;
    const int wm = wid & 3;
    const int wn = wid >> 2;

    float d[2][8][4];
    #pragma unroll
    for (int mi = 0; mi < 2; mi++)
        #pragma unroll
        for (int ni = 0; ni < 8; ni++)
            #pragma unroll
            for (int p = 0; p < 4; p++) d[mi][ni][p] = 0.f;

    for (int kc = 0; kc < 128; kc += 64) {
        #pragma unroll
        for (int i = t; i < 2048; i += 256) {
            int r = i >> 4, c4 = i & 15;
            int gr = row0 + r;
            if (F16IN) {
                uint2 raw = make_uint2(0u, 0u);
                if (gr < NN)
                    raw = *reinterpret_cast<const uint2*>(
                        (const __half*)Ap + (size_t)gr * 128 + kc + c4 * 4);
                *reinterpret_cast<uint2*>(&sm.a[r][c4 * 4]) = raw;
            } else {
                float4 v = make_float4(0.f, 0.f, 0.f, 0.f);
                if (gr < NN)
                    v = *reinterpret_cast<const float4*>(
                        (const float*)Ap + (size_t)gr * 128 + kc + c4 * 4);
                __half2 h01 = __floats2half2_rn(v.x, v.y);
                __half2 h23 = __floats2half2_rn(v.z, v.w);
                uint2 raw;
                raw.x = *reinterpret_cast<unsigned*>(&h01);
                raw.y = *reinterpret_cast<unsigned*>(&h23);
                *reinterpret_cast<uint2*>(&sm.a[r][c4 * 4]) = raw;
            }
        }
        #pragma unroll
        for (int i = t; i < 2048; i += 256) {
            int r = i >> 5, c4 = i & 31;
            float4 v = *reinterpret_cast<const float4*>(&W[(size_t)(kc + r) * 128 + c4 * 4]);
            __half2 h01 = __floats2half2_rn(v.x, v.y);
            __half2 h23 = __floats2half2_rn(v.z, v.w);
            uint2 raw;
            raw.x = *reinterpret_cast<unsigned*>(&h01);
            raw.y = *reinterpret_cast<unsigned*>(&h23);
            *reinterpret_cast<uint2*>(&sm.w[r][c4 * 4]) = raw;
        }
        __syncthreads();

        #pragma unroll
        for (int ks = 0; ks < 4; ks++) {
            const int k0 = ks * 16;
            unsigned a0[4], a1[4];
            ldsm_x4(a0[0], a0[1], a0[2], a0[3],
                    &sm.a[wm * 32 + (lane & 15)][k0 + ((lane >> 4) & 1) * 8]);
            ldsm_x4(a1[0], a1[1], a1[2], a1[3],
                    &sm.a[wm * 32 + 16 + (lane & 15)][k0 + ((lane >> 4) & 1) * 8]);
            #pragma unroll
            for (int np = 0; np < 4; np++) {
                unsigned b[4];
                ldsm_x4_t(b[0], b[1], b[2], b[3],
                          &sm.w[k0 + (lane & 7) + ((lane >> 3) & 1) * 8]
                               [wn * 64 + np * 16 + (lane >> 4) * 8]);
                mma16816(d[0][2 * np],     a0, b[0], b[1]);
                mma16816(d[0][2 * np + 1], a0, b[2], b[3]);
                mma16816(d[1][2 * np],     a1, b[0], b[1]);
                mma16816(d[1][2 * np + 1], a1, b[2], b[3]);
            }
        }
        __syncthreads();
    }

    // ---- row-max for int8 scales ----
    if (t < 128) sm.rmax[t] = 0.f;
    __syncthreads();
    float lm[4] = {0.f, 0.f, 0.f, 0.f};   // rows rA, rA+8, rA+16, rA+24
    #pragma unroll
    for (int mi = 0; mi < 2; mi++)
        #pragma unroll
        for (int ni = 0; ni < 8; ni++) {
            lm[mi * 2]     = fmaxf(lm[mi * 2],     fmaxf(fabsf(d[mi][ni][0]), fabsf(d[mi][ni][1])));
            lm[mi * 2 + 1] = fmaxf(lm[mi * 2 + 1], fmaxf(fabsf(d[mi][ni][2]), fabsf(d[mi][ni][3])));
        }
    #pragma unroll
    for (int p = 0; p < 4; p++) {
        lm[p] = fmaxf(lm[p], __shfl_xor_sync(0xFFFFFFFFu, lm[p], 1));
        lm[p] = fmaxf(lm[p], __shfl_xor_sync(0xFFFFFFFFu, lm[p], 2));
    }
    if ((lane & 3) == 0) {
        int rA = wm * 32 + (lane >> 2);
        atomicMax(reinterpret_cast<int*>(&sm.rmax[rA]),      __float_as_int(lm[0]));
        atomicMax(reinterpret_cast<int*>(&sm.rmax[rA + 8]),  __float_as_int(lm[1]));
        atomicMax(reinterpret_cast<int*>(&sm.rmax[rA + 16]), __float_as_int(lm[2]));
        atomicMax(reinterpret_cast<int*>(&sm.rmax[rA + 24]), __float_as_int(lm[3]));
    }
    __syncthreads();
    if (t < 128) {
        int gr = row0 + t;
        if (gr < NN) SCL[gr] = sm.rmax[t] * (1.f / 127.f);
    }

    // ---- epilogue: fp16 + int8 stores ----
    #pragma unroll
    for (int mi = 0; mi < 2; mi++) {
        int rlocA = wm * 32 + mi * 16 + (lane >> 2);
        int rowA = row0 + rlocA;
        int rowB = rowA + 8;
        float rmA = sm.rmax[rlocA],     invA = rmA > 0.f ? 127.f / rmA : 0.f;
        float rmB = sm.rmax[rlocA + 8], invB = rmB > 0.f ? 127.f / rmB : 0.f;
        #pragma unroll
        for (int ni = 0; ni < 8; ni++) {
            int col = wn * 64 + ni * 8 + (lane & 3) * 2;
            if (rowA < NN) {
                __half2 h = __floats2half2_rn(d[mi][ni][0], d[mi][ni][1]);
                *reinterpret_cast<__half2*>(&C16[(size_t)rowA * 128 + col]) = h;
                char q0 = (char)__float2int_rn(d[mi][ni][0] * invA);
                char q1 = (char)__float2int_rn(d[mi][ni][1] * invA);
                *reinterpret_cast<char2*>(&Q8[(size_t)rowA * 128 + col]) = make_char2(q0, q1);
            }
            if (rowB < NN) {
                __half2 h = __floats2half2_rn(d[mi][ni][2], d[mi][ni][3]);
                *reinterpret_cast<__half2*>(&C16[(size_t)rowB * 128 + col]) = h;
                char q2 = (char)__float2int_rn(d[mi][ni][2] * invB);
                char q3 = (char)__float2int_rn(d[mi][ni][3] * invB);
                *reinterpret_cast<char2*>(&Q8[(size_t)rowB * 128 + col]) = make_char2(q2, q3);
            }
        }
    }
}

__global__ void __launch_bounds__(256) gemm32_kernel(const float* __restrict__ A,
                                                     const float* __restrict__ W,
                                                     __half* __restrict__ C16,
                                                     char* __restrict__ Q8,
                                                     float* __restrict__ SCL) {
    __shared__ HSmem sm;
    gemm_hmma_body<false>(sm, A, W, C16, Q8, SCL, blockIdx.x * 128, threadIdx.x);
}

__global__ void __launch_bounds__(256) gemm16_kernel(const __half* __restrict__ A16,
                                                     const float* __restrict__ W,
                                                     __half* __restrict__ C16,
                                                     char* __restrict__ Q8,
                                                     float* __restrict__ SCL) {
    __shared__ HSmem sm;
    gemm_hmma_body<true>(sm, A16, W, C16, Q8, SCL, blockIdx.x * 128, threadIdx.x);
}

// ---------------- CSR build (R9 form: packed int2 fill) ----------------
__global__ void count_kernel(const int* __restrict__ dst) {
    int e = blockIdx.x * blockDim.x + threadIdx.x;
    if (e < EE) atomicAdd(&g_deg[dst[e]], 1);
}

__global__ void fill_kernel(const int* __restrict__ src, const int* __restrict__ dst) {
    int e = blockIdx.x * blockDim.x + threadIdx.x;
    if (e < EE) {
        int d = dst[e];
        int s = src[e];
        int pos = atomicAdd(&g_cursor[d], 1);
        int2 pk;
        pk.x = s;
        pk.y = __float_as_int(g_dinv[s] * g_dinv[d]);
        g_epack[pos] = pk;
    }
}

__global__ void __launch_bounds__(512) blocksum_kernel() {
    __shared__ int wsum[16];
    int t = threadIdx.x, lane = t & 31, wid = t >> 5;
    int i = blockIdx.x * 512 + t;
    int v = (i < NN) ? g_deg[i] : 0;
    #pragma unroll
    for (int d = 16; d > 0; d >>= 1)
        v += __shfl_xor_sync(0xFFFFFFFFu, v, d);
    if (lane == 0) wsum[wid] = v;
    __syncthreads();
    if (wid == 0) {
        int s = (lane < 16) ? wsum[lane] : 0;
        #pragma unroll
        for (int d = 8; d > 0; d >>= 1)
            s += __shfl_xor_sync(0xFFFFFFFFu, s, d);
        if (lane == 0) g_bsum[blockIdx.x] = s;
    }
}

__global__ void __launch_bounds__(512) rowptr_kernel() {
    __shared__ int wsum[16];
    __shared__ int s_base;
    int t = threadIdx.x, lane = t & 31, wid = t >> 5;

    int pre = 0;
    for (int j = t; j < blockIdx.x; j += 512) pre += g_bsum[j];
    #pragma unroll
    for (int d = 16; d > 0; d >>= 1)
        pre += __shfl_xor_sync(0xFFFFFFFFu, pre, d);
    if (lane == 0) wsum[wid] = pre;
    __syncthreads();
    if (t == 0) {
        int b = 0;
        #pragma unroll
        for (int w = 0; w < 16; w++) b += wsum[w];
        s_base = b;
    }
    __syncthreads();
    const int base = s_base;
    __syncthreads();

    int i = blockIdx.x * 512 + t;
    int v = (i < NN) ? g_deg[i] : 0;
    int inc = v;
    #pragma unroll
    for (int d = 1; d < 32; d <<= 1) {
        int u = __shfl_up_sync(0xFFFFFFFFu, inc, d);
        if (lane >= d) inc += u;
    }
    if (lane == 31) wsum[wid] = inc;
    __syncthreads();
    if (wid == 0) {
        int s = (lane < 16) ? wsum[lane] : 0;
        int si = s;
        #pragma unroll
        for (int d = 1; d < 16; d <<= 1) {
            int u = __shfl_up_sync(0xFFFFFFFFu, si, d);
            if (lane >= d) si += u;
        }
        if (lane < 16) wsum[lane] = si - s;
    }
    __syncthreads();
    int incl = base + wsum[wid] + inc;
    if (i < NN) {
        g_rowptr[i + 1] = incl;
        g_cursor[i] = incl - v;
        g_dinv[i] = rsqrtf((float)v + 1.0f);
        g_deg[i] = 0;
    }
    if (i == 0) g_rowptr[0] = 0;
}

// ---------------- aggregation: warp/node, int8 gathers + fp16 self, fp32 accum ----------------
__global__ void __launch_bounds__(256) agg_kernel(const __half* __restrict__ hp16,
                                                  const char* __restrict__ hq8,
                                                  const float* __restrict__ hscl,
                                                  const float* __restrict__ bias,
                                                  __half* __restrict__ hout16) {
    int warp = (blockIdx.x * blockDim.x + threadIdx.x) >> 5;
    int lane = threadIdx.x & 31;
    if (warp >= NN) return;
    const int u = warp;
    const float du = g_dinv[u];

    uint2 sraw = *reinterpret_cast<const uint2*>(hp16 + (size_t)u * 128 + lane * 4);
    float2 s0 = __half22float2(*reinterpret_cast<__half2*>(&sraw.x));
    float2 s1 = __half22float2(*reinterpret_cast<__half2*>(&sraw.y));
    const unsigned long long selfc = pk2(du * du, du * du);
    ulonglong2 acc;
    acc.x = fma2(pk2(s0.x, s0.y), selfc, 0ULL);
    acc.y = fma2(pk2(s1.x, s1.y), selfc, 0ULL);

    const int beg = g_rowptr[u], end = g_rowptr[u + 1];
    for (int base = beg; base < end; base += 32) {
        int rem = end - base;
        int n = rem < 32 ? rem : 32;
        int s = 0; float c = 0.f;
        if (lane < n) {
            int2 pk = g_epack[base + lane];
            s = pk.x;
            c = __int_as_float(pk.y) * hscl[pk.x];   // fold dequant scale into edge coef
        }
        #pragma unroll 8
        for (int k = 0; k < n; k++) {
            int   sk = __shfl_sync(0xFFFFFFFFu, s, k);
            float ck = __shfl_sync(0xFFFFFFFFu, c, k);
            int w = __ldg(reinterpret_cast<const int*>(hq8 + (size_t)sk * 128) + lane);
            float f0 = (float)(signed char)(w);
            float f1 = (float)(signed char)(w >> 8);
            float f2 = (float)(signed char)(w >> 16);
            float f3 = (float)(signed char)(w >> 24);
            unsigned long long cc = pk2(ck, ck);
            acc.x = fma2(pk2(f0, f1), cc, acc.x);
            acc.y = fma2(pk2(f2, f3), cc, acc.y);
        }
    }
    float4 bb = *reinterpret_cast<const float4*>(&bias[lane * 4]);
    float2 a0 = upk(acc.x), a1 = upk(acc.y);
    __half2 o0 = __floats2half2_rn(fmaxf(a0.x + bb.x, 0.f), fmaxf(a0.y + bb.y, 0.f));
    __half2 o1 = __floats2half2_rn(fmaxf(a1.x + bb.z, 0.f), fmaxf(a1.y + bb.w, 0.f));
    uint2 oraw;
    oraw.x = *reinterpret_cast<unsigned*>(&o0);
    oraw.y = *reinterpret_cast<unsigned*>(&o1);
    *reinterpret_cast<uint2*>(hout16 + (size_t)u * 128 + lane * 4) = oraw;
}

// ---------------- final: HMMA [h1|h2]@Wlin + blin, fused log_softmax ----------------
struct OutHS { __half a[128][72]; __half w[64][56]; };
union OutU { OutHS g; float logits[128][41]; };

__global__ void __launch_bounds__(256) gemmout_kernel(const __half* __restrict__ h1,
                                                      const __half* __restrict__ h2,
                                                      const float* __restrict__ Wlin,
                                                      const float* __restrict__ blin,
                                                      float* __restrict__ out) {
    __shared__ OutU sm;
    const int t = threadIdx.x;
    const int lane = t & 31, wid = t >> 5;
    const int row0 = blockIdx.x * 128;

    float d[6][4];
    #pragma unroll
    for (int ni = 0; ni < 6; ni++)
        #pragma unroll
        for (int p = 0; p < 4; p++) d[ni][p] = 0.f;

    #pragma unroll
    for (int chunk = 0; chunk < 4; chunk++) {
        const __half* hsrc = (chunk < 2) ? h1 : h2;
        const int koff = (chunk & 1) * 64;
        const int kc = chunk * 64;
        #pragma unroll
        for (int i = t; i < 2048; i += 256) {
            int r = i >> 4, c4 = i & 15;
            int gr = row0 + r;
            uint2 raw = make_uint2(0u, 0u);
            if (gr < NN)
                raw = *reinterpret_cast<const uint2*>(&hsrc[(size_t)gr * 128 + koff + c4 * 4]);
            *reinterpret_cast<uint2*>(&sm.g.a[r][c4 * 4]) = raw;
        }
        #pragma unroll
        for (int i = t; i < 3584; i += 256) {
            int r = i / 56, c = i % 56;
            float v = (c < 40) ? Wlin[(size_t)(kc + r) * 40 + c] : 0.f;
            sm.g.w[r][c] = __float2half(v);
        }
        __syncthreads();
        #pragma unroll
        for (int ks = 0; ks < 4; ks++) {
            const int k0 = ks * 16;
            unsigned a[4];
            ldsm_x4(a[0], a[1], a[2], a[3],
                    &sm.g.a[wid * 16 + (lane & 15)][k0 + ((lane >> 4) & 1) * 8]);
            #pragma unroll
            for (int np = 0; np < 3; np++) {
                unsigned b[4];
                ldsm_x4_t(b[0], b[1], b[2], b[3],
                          &sm.g.w[k0 + (lane & 7) + ((lane >> 3) & 1) * 8]
                               [np * 16 + (lane >> 4) * 8]);
                mma16816(d[2 * np],     a, b[0], b[1]);
                mma16816(d[2 * np + 1], a, b[2], b[3]);
            }
        }
        __syncthreads();
    }

    {
        int r0 = wid * 16 + (lane >> 2);
        #pragma unroll
        for (int ni = 0; ni < 6; ni++) {
            int col = ni * 8 + (lane & 3) * 2;
            if (col < 40) {
                float b0 = blin[col], b1 = blin[col + 1];
                sm.logits[r0][col]         = d[ni][0] + b0;
                sm.logits[r0][col + 1]     = d[ni][1] + b1;
                sm.logits[r0 + 8][col]     = d[ni][2] + b0;
                sm.logits[r0 + 8][col + 1] = d[ni][3] + b1;
            }
        }
    }
    __syncthreads();

    if (t < 128) {
        int gr = row0 + t;
        if (gr < NN) {
            float m = -INFINITY;
            #pragma unroll
            for (int c = 0; c < 40; c++) m = fmaxf(m, sm.logits[t][c]);
            float s = 0.f;
            #pragma unroll
            for (int c = 0; c < 40; c++) s += expf(sm.logits[t][c] - m);
            float lse = m + logf(s);
            float* po = out + (size_t)gr * 40;
            #pragma unroll
            for (int c = 0; c < 40; c += 4) {
                float4 v = make_float4(sm.logits[t][c]     - lse,
                                       sm.logits[t][c + 1] - lse,
                                       sm.logits[t][c + 2] - lse,
                                       sm.logits[t][c + 3] - lse);
                *reinterpret_cast<float4*>(po + c) = v;
            }
        }
    }
}

// ---------------- launch ----------------
extern "C" void kernel_launch(void* const* d_in, const int* in_sizes, int n_in,
                              void* d_out, int out_size) {
    const float* x    = (const float*)d_in[0];
    const int*   ei   = (const int*)d_in[1];
    const float* W1   = (const float*)d_in[2];
    const float* b1   = (const float*)d_in[3];
    const float* W2   = (const float*)d_in[4];
    const float* b2   = (const float*)d_in[5];
    const float* Wlin = (const float*)d_in[6];
    const float* blin = (const float*)d_in[7];
    float* out = (float*)d_out;

    const int* src = ei;        // edge_index[0]
    const int* dst = ei + EE;   // edge_index[1]

    __half *p_hpre16, *p_h116, *p_h216;
    char* p_hq8;
    float* p_hscl;
    cudaGetSymbolAddress((void**)&p_hpre16, g_hpre16);
    cudaGetSymbolAddress((void**)&p_hq8, g_hq8);
    cudaGetSymbolAddress((void**)&p_hscl, g_hscl);
    cudaGetSymbolAddress((void**)&p_h116, g_h116);
    cudaGetSymbolAddress((void**)&p_h216, g_h216);

    const int NB_W = (NN * 32 + 255) / 256;   // warp-per-node grids

    count_kernel<<<NB_E, 256>>>(dst);                                        // 1
    blocksum_kernel<<<NBLK, 512>>>();                                         // 2
    rowptr_kernel<<<NBLK, 512>>>();                                           // 3
    fill_kernel<<<NB_E, 256>>>(src, dst);                                     // 4 (ncu target)
    gemm32_kernel<<<GFULL, 256>>>(x, W1, p_hpre16, p_hq8, p_hscl);            // 5
    agg_kernel<<<NB_W, 256>>>(p_hpre16, p_hq8, p_hscl, b1, p_h116);           // 6
    gemm16_kernel<<<GFULL, 256>>>(p_h116, W2, p_hpre16, p_hq8, p_hscl);       // 7
    agg_kernel<<<NB_W, 256>>>(p_hpre16, p_hq8, p_hscl, b2, p_h216);           // 8
    gemmout_kernel<<<GFULL, 256>>>(p_h116, p_h216, Wlin, blin, out);          // 9
}

// round 15
// speedup vs baseline: 1.1957x; 1.1957x over previous
#include <cuda_runtime.h>
#include <cuda_fp16.h>
#include <math.h>

#define NN 100000
#define EE 1600000
#define HH 128
#define CC 40
#define NBLK 196        // ceil(100000/512)
#define GFULL 782       // ceil(100000/128)
#define NB_E 6250       // ceil(EE/256)

// ---------------- scratch (no allocations allowed) ----------------
__device__ __half g_hpre16[NN * HH];
__device__ __half g_h116[NN * HH];
__device__ __half g_h216[NN * HH];
__device__ float  g_dinv[NN];
__device__ int    g_deg[NN];          // invariant: zero at launch entry
__device__ int    g_rowptr[NN + 1];
__device__ int    g_cursor[NN];
__device__ int2   g_epack[EE];        // (src, __float_as_int(coef))
__device__ int    g_bsum[NBLK];

// ---------------- f32x2 helpers ----------------
__device__ __forceinline__ unsigned long long fma2(unsigned long long a,
                                                   unsigned long long b,
                                                   unsigned long long c) {
    unsigned long long d;
    asm("fma.rn.f32x2 %0, %1, %2, %3;" : "=l"(d) : "l"(a), "l"(b), "l"(c));
    return d;
}
__device__ __forceinline__ unsigned long long pk2(float lo, float hi) {
    unsigned long long d;
    asm("mov.b64 %0, {%1, %2};" : "=l"(d) : "f"(lo), "f"(hi));
    return d;
}
__device__ __forceinline__ float2 upk(unsigned long long v) {
    float2 r;
    asm("mov.b64 {%0, %1}, %2;" : "=f"(r.x), "=f"(r.y) : "l"(v));
    return r;
}

// ---------------- HMMA helpers ----------------
__device__ __forceinline__ void ldsm_x4(unsigned& r0, unsigned& r1, unsigned& r2, unsigned& r3,
                                        const void* p) {
    unsigned addr = (unsigned)__cvta_generic_to_shared(p);
    asm volatile("ldmatrix.sync.aligned.m8n8.x4.shared.b16 {%0,%1,%2,%3}, [%4];"
                 : "=r"(r0), "=r"(r1), "=r"(r2), "=r"(r3) : "r"(addr));
}
__device__ __forceinline__ void ldsm_x4_t(unsigned& r0, unsigned& r1, unsigned& r2, unsigned& r3,
                                          const void* p) {
    unsigned addr = (unsigned)__cvta_generic_to_shared(p);
    asm volatile("ldmatrix.sync.aligned.m8n8.x4.trans.shared.b16 {%0,%1,%2,%3}, [%4];"
                 : "=r"(r0), "=r"(r1), "=r"(r2), "=r"(r3) : "r"(addr));
}
__device__ __forceinline__ void mma16816(float* d, const unsigned* a, unsigned b0, unsigned b1) {
    asm volatile("mma.sync.aligned.m16n8k16.row.col.f32.f16.f16.f32 "
                 "{%0,%1,%2,%3}, {%4,%5,%6,%7}, {%8,%9}, {%0,%1,%2,%3};"
                 : "+f"(d[0]), "+f"(d[1]), "+f"(d[2]), "+f"(d[3])
                 : "r"(a[0]), "r"(a[1]), "r"(a[2]), "r"(a[3]), "r"(b0), "r"(b1));
}

// ---------------- HMMA gemm body: C16[rows,128] = A[rows,128] @ W[128,128] ----------------
struct HSmem { __half a[128][72]; __half w[64][136]; };

template <bool F16IN>
__device__ __forceinline__ void gemm_hmma_body(HSmem& sm,
                                               const void* __restrict__ Ap,
                                               const float* __restrict__ W,
                                               __half* __restrict__ C16,
                                               int row0, int t) {
    const int lane = t & 31, wid = t >> 5;
    const int wm = wid & 3;
    const int wn = wid >> 2;

    float d[2][8][4];
    #pragma unroll
    for (int mi = 0; mi < 2; mi++)
        #pragma unroll
        for (int ni = 0; ni < 8; ni++)
            #pragma unroll
            for (int p = 0; p < 4; p++) d[mi][ni][p] = 0.f;

    for (int kc = 0; kc < 128; kc += 64) {
        #pragma unroll
        for (int i = t; i < 2048; i += 256) {
            int r = i >> 4, c4 = i & 15;
            int gr = row0 + r;
            if (F16IN) {
                uint2 raw = make_uint2(0u, 0u);
                if (gr < NN)
                    raw = *reinterpret_cast<const uint2*>(
                        (const __half*)Ap + (size_t)gr * 128 + kc + c4 * 4);
                *reinterpret_cast<uint2*>(&sm.a[r][c4 * 4]) = raw;
            } else {
                float4 v = make_float4(0.f, 0.f, 0.f, 0.f);
                if (gr < NN)
                    v = *reinterpret_cast<const float4*>(
                        (const float*)Ap + (size_t)gr * 128 + kc + c4 * 4);
                __half2 h01 = __floats2half2_rn(v.x, v.y);
                __half2 h23 = __floats2half2_rn(v.z, v.w);
                uint2 raw;
                raw.x = *reinterpret_cast<unsigned*>(&h01);
                raw.y = *reinterpret_cast<unsigned*>(&h23);
                *reinterpret_cast<uint2*>(&sm.a[r][c4 * 4]) = raw;
            }
        }
        #pragma unroll
        for (int i = t; i < 2048; i += 256) {
            int r = i >> 5, c4 = i & 31;
            float4 v = *reinterpret_cast<const float4*>(&W[(size_t)(kc + r) * 128 + c4 * 4]);
            __half2 h01 = __floats2half2_rn(v.x, v.y);
            __half2 h23 = __floats2half2_rn(v.z, v.w);
            uint2 raw;
            raw.x = *reinterpret_cast<unsigned*>(&h01);
            raw.y = *reinterpret_cast<unsigned*>(&h23);
            *reinterpret_cast<uint2*>(&sm.w[r][c4 * 4]) = raw;
        }
        __syncthreads();

        #pragma unroll
        for (int ks = 0; ks < 4; ks++) {
            const int k0 = ks * 16;
            unsigned a0[4], a1[4];
            ldsm_x4(a0[0], a0[1], a0[2], a0[3],
                    &sm.a[wm * 32 + (lane & 15)][k0 + ((lane >> 4) & 1) * 8]);
            ldsm_x4(a1[0], a1[1], a1[2], a1[3],
                    &sm.a[wm * 32 + 16 + (lane & 15)][k0 + ((lane >> 4) & 1) * 8]);
            #pragma unroll
            for (int np = 0; np < 4; np++) {
                unsigned b[4];
                ldsm_x4_t(b[0], b[1], b[2], b[3],
                          &sm.w[k0 + (lane & 7) + ((lane >> 3) & 1) * 8]
                               [wn * 64 + np * 16 + (lane >> 4) * 8]);
                mma16816(d[0][2 * np],     a0, b[0], b[1]);
                mma16816(d[0][2 * np + 1], a0, b[2], b[3]);
                mma16816(d[1][2 * np],     a1, b[0], b[1]);
                mma16816(d[1][2 * np + 1], a1, b[2], b[3]);
            }
        }
        __syncthreads();
    }

    #pragma unroll
    for (int mi = 0; mi < 2; mi++) {
        int row = row0 + wm * 32 + mi * 16 + (lane >> 2);
        #pragma unroll
        for (int ni = 0; ni < 8; ni++) {
            int col = wn * 64 + ni * 8 + (lane & 3) * 2;
            if (row < NN) {
                __half2 h = __floats2half2_rn(d[mi][ni][0], d[mi][ni][1]);
                *reinterpret_cast<__half2*>(&C16[(size_t)row * 128 + col]) = h;
            }
            if (row + 8 < NN) {
                __half2 h = __floats2half2_rn(d[mi][ni][2], d[mi][ni][3]);
                *reinterpret_cast<__half2*>(&C16[(size_t)(row + 8) * 128 + col]) = h;
            }
        }
    }
}

__global__ void __launch_bounds__(256) gemm32_kernel(const float* __restrict__ A,
                                                     const float* __restrict__ W,
                                                     __half* __restrict__ C16) {
    __shared__ HSmem sm;
    gemm_hmma_body<false>(sm, A, W, C16, blockIdx.x * 128, threadIdx.x);
}

__global__ void __launch_bounds__(256) gemm16_kernel(const __half* __restrict__ A16,
                                                     const float* __restrict__ W,
                                                     __half* __restrict__ C16) {
    __shared__ HSmem sm;
    gemm_hmma_body<true>(sm, A16, W, C16, blockIdx.x * 128, threadIdx.x);
}

// ---------------- CSR build ----------------
__global__ void count_kernel(const int* __restrict__ dst) {
    int e = blockIdx.x * blockDim.x + threadIdx.x;
    if (e < EE) atomicAdd(&g_deg[dst[e]], 1);
}

__global__ void fill_kernel(const int* __restrict__ src, const int* __restrict__ dst) {
    int e = blockIdx.x * blockDim.x + threadIdx.x;
    if (e < EE) {
        int d = dst[e];
        int s = src[e];
        int pos = atomicAdd(&g_cursor[d], 1);
        int2 pk;
        pk.x = s;
        pk.y = __float_as_int(g_dinv[s] * g_dinv[d]);
        g_epack[pos] = pk;
    }
}

__global__ void __launch_bounds__(512) blocksum_kernel() {
    __shared__ int wsum[16];
    int t = threadIdx.x, lane = t & 31, wid = t >> 5;
    int i = blockIdx.x * 512 + t;
    int v = (i < NN) ? g_deg[i] : 0;
    #pragma unroll
    for (int d = 16; d > 0; d >>= 1)
        v += __shfl_xor_sync(0xFFFFFFFFu, v, d);
    if (lane == 0) wsum[wid] = v;
    __syncthreads();
    if (wid == 0) {
        int s = (lane < 16) ? wsum[lane] : 0;
        #pragma unroll
        for (int d = 8; d > 0; d >>= 1)
            s += __shfl_xor_sync(0xFFFFFFFFu, s, d);
        if (lane == 0) g_bsum[blockIdx.x] = s;
    }
}

__global__ void __launch_bounds__(512) rowptr_kernel() {
    __shared__ int wsum[16];
    __shared__ int s_base;
    int t = threadIdx.x, lane = t & 31, wid = t >> 5;

    int pre = 0;
    for (int j = t; j < blockIdx.x; j += 512) pre += g_bsum[j];
    #pragma unroll
    for (int d = 16; d > 0; d >>= 1)
        pre += __shfl_xor_sync(0xFFFFFFFFu, pre, d);
    if (lane == 0) wsum[wid] = pre;
    __syncthreads();
    if (t == 0) {
        int b = 0;
        #pragma unroll
        for (int w = 0; w < 16; w++) b += wsum[w];
        s_base = b;
    }
    __syncthreads();
    const int base = s_base;
    __syncthreads();

    int i = blockIdx.x * 512 + t;
    int v = (i < NN) ? g_deg[i] : 0;
    int inc = v;
    #pragma unroll
    for (int d = 1; d < 32; d <<= 1) {
        int u = __shfl_up_sync(0xFFFFFFFFu, inc, d);
        if (lane >= d) inc += u;
    }
    if (lane == 31) wsum[wid] = inc;
    __syncthreads();
    if (wid == 0) {
        int s = (lane < 16) ? wsum[lane] : 0;
        int si = s;
        #pragma unroll
        for (int d = 1; d < 16; d <<= 1) {
            int u = __shfl_up_sync(0xFFFFFFFFu, si, d);
            if (lane >= d) si += u;
        }
        if (lane < 16) wsum[lane] = si - s;
    }
    __syncthreads();
    int incl = base + wsum[wid] + inc;
    if (i < NN) {
        g_rowptr[i + 1] = incl;
        g_cursor[i] = incl - v;
        g_dinv[i] = rsqrtf((float)v + 1.0f);
        g_deg[i] = 0;
    }
    if (i == 0) g_rowptr[0] = 0;
}

// ---------------- aggregation: R9 form (warp/node, uint2 fp16 gathers, fp32 accum) ----------------
__global__ void __launch_bounds__(256) agg_kernel(const __half* __restrict__ hp16,
                                                  const float* __restrict__ bias,
                                                  __half* __restrict__ hout16) {
    int warp = (blockIdx.x * blockDim.x + threadIdx.x) >> 5;
    int lane = threadIdx.x & 31;
    if (warp >= NN) return;
    const int u = warp;
    const float du = g_dinv[u];

    uint2 sraw = *reinterpret_cast<const uint2*>(hp16 + (size_t)u * 128 + lane * 4);
    float2 s0 = __half22float2(*reinterpret_cast<__half2*>(&sraw.x));
    float2 s1 = __half22float2(*reinterpret_cast<__half2*>(&sraw.y));
    const unsigned long long selfc = pk2(du * du, du * du);
    ulonglong2 acc;
    acc.x = fma2(pk2(s0.x, s0.y), selfc, 0ULL);
    acc.y = fma2(pk2(s1.x, s1.y), selfc, 0ULL);

    const int beg = g_rowptr[u], end = g_rowptr[u + 1];
    for (int base = beg; base < end; base += 32) {
        int rem = end - base;
        int n = rem < 32 ? rem : 32;
        int s = 0; float c = 0.f;
        if (lane < n) {
            int2 pk = g_epack[base + lane];
            s = pk.x;
            c = __int_as_float(pk.y);
        }
        #pragma unroll 8
        for (int k = 0; k < n; k++) {
            int   sk = __shfl_sync(0xFFFFFFFFu, s, k);
            float ck = __shfl_sync(0xFFFFFFFFu, c, k);
            uint2 raw = __ldg(reinterpret_cast<const uint2*>(hp16 + (size_t)sk * 128) + lane);
            float2 f0 = __half22float2(*reinterpret_cast<__half2*>(&raw.x));
            float2 f1 = __half22float2(*reinterpret_cast<__half2*>(&raw.y));
            unsigned long long cc = pk2(ck, ck);
            acc.x = fma2(pk2(f0.x, f0.y), cc, acc.x);
            acc.y = fma2(pk2(f1.x, f1.y), cc, acc.y);
        }
    }
    float4 bb = *reinterpret_cast<const float4*>(&bias[lane * 4]);
    float2 a0 = upk(acc.x), a1 = upk(acc.y);
    __half2 o0 = __floats2half2_rn(fmaxf(a0.x + bb.x, 0.f), fmaxf(a0.y + bb.y, 0.f));
    __half2 o1 = __floats2half2_rn(fmaxf(a1.x + bb.z, 0.f), fmaxf(a1.y + bb.w, 0.f));
    uint2 oraw;
    oraw.x = *reinterpret_cast<unsigned*>(&o0);
    oraw.y = *reinterpret_cast<unsigned*>(&o1);
    *reinterpret_cast<uint2*>(hout16 + (size_t)u * 128 + lane * 4) = oraw;
}

// ---------------- final: HMMA [h1|h2]@Wlin + blin, fused log_softmax ----------------
struct OutHS { __half a[128][72]; __half w[64][56]; };
union OutU { OutHS g; float logits[128][41]; };

__global__ void __launch_bounds__(256) gemmout_kernel(const __half* __restrict__ h1,
                                                      const __half* __restrict__ h2,
                                                      const float* __restrict__ Wlin,
                                                      const float* __restrict__ blin,
                                                      float* __restrict__ out) {
    __shared__ OutU sm;
    const int t = threadIdx.x;
    const int lane = t & 31, wid = t >> 5;
    const int row0 = blockIdx.x * 128;

    float d[6][4];
    #pragma unroll
    for (int ni = 0; ni < 6; ni++)
        #pragma unroll
        for (int p = 0; p < 4; p++) d[ni][p] = 0.f;

    #pragma unroll
    for (int chunk = 0; chunk < 4; chunk++) {
        const __half* hsrc = (chunk < 2) ? h1 : h2;
        const int koff = (chunk & 1) * 64;
        const int kc = chunk * 64;
        #pragma unroll
        for (int i = t; i < 2048; i += 256) {
            int r = i >> 4, c4 = i & 15;
            int gr = row0 + r;
            uint2 raw = make_uint2(0u, 0u);
            if (gr < NN)
                raw = *reinterpret_cast<const uint2*>(&hsrc[(size_t)gr * 128 + koff + c4 * 4]);
            *reinterpret_cast<uint2*>(&sm.g.a[r][c4 * 4]) = raw;
        }
        #pragma unroll
        for (int i = t; i < 3584; i += 256) {
            int r = i / 56, c = i % 56;
            float v = (c < 40) ? Wlin[(size_t)(kc + r) * 40 + c] : 0.f;
            sm.g.w[r][c] = __float2half(v);
        }
        __syncthreads();
        #pragma unroll
        for (int ks = 0; ks < 4; ks++) {
            const int k0 = ks * 16;
            unsigned a[4];
            ldsm_x4(a[0], a[1], a[2], a[3],
                    &sm.g.a[wid * 16 + (lane & 15)][k0 + ((lane >> 4) & 1) * 8]);
            #pragma unroll
            for (int np = 0; np < 3; np++) {
                unsigned b[4];
                ldsm_x4_t(b[0], b[1], b[2], b[3],
                          &sm.g.w[k0 + (lane & 7) + ((lane >> 3) & 1) * 8]
                               [np * 16 + (lane >> 4) * 8]);
                mma16816(d[2 * np],     a, b[0], b[1]);
                mma16816(d[2 * np + 1], a, b[2], b[3]);
            }
        }
        __syncthreads();
    }

    {
        int r0 = wid * 16 + (lane >> 2);
        #pragma unroll
        for (int ni = 0; ni < 6; ni++) {
            int col = ni * 8 + (lane & 3) * 2;
            if (col < 40) {
                float b0 = blin[col], b1 = blin[col + 1];
                sm.logits[r0][col]         = d[ni][0] + b0;
                sm.logits[r0][col + 1]     = d[ni][1] + b1;
                sm.logits[r0 + 8][col]     = d[ni][2] + b0;
                sm.logits[r0 + 8][col + 1] = d[ni][3] + b1;
            }
        }
    }
    __syncthreads();

    if (t < 128) {
        int gr = row0 + t;
        if (gr < NN) {
            float m = -INFINITY;
            #pragma unroll
            for (int c = 0; c < 40; c++) m = fmaxf(m, sm.logits[t][c]);
            float s = 0.f;
            #pragma unroll
            for (int c = 0; c < 40; c++) s += expf(sm.logits[t][c] - m);
            float lse = m + logf(s);
            float* po = out + (size_t)gr * 40;
            #pragma unroll
            for (int c = 0; c < 40; c += 4) {
                float4 v = make_float4(sm.logits[t][c]     - lse,
                                       sm.logits[t][c + 1] - lse,
                                       sm.logits[t][c + 2] - lse,
                                       sm.logits[t][c + 3] - lse);
                *reinterpret_cast<float4*>(po + c) = v;
            }
        }
    }
}

// ---------------- launch ----------------
extern "C" void kernel_launch(void* const* d_in, const int* in_sizes, int n_in,
                              void* d_out, int out_size) {
    const float* x    = (const float*)d_in[0];
    const int*   ei   = (const int*)d_in[1];
    const float* W1   = (const float*)d_in[2];
    const float* b1   = (const float*)d_in[3];
    const float* W2   = (const float*)d_in[4];
    const float* b2   = (const float*)d_in[5];
    const float* Wlin = (const float*)d_in[6];
    const float* blin = (const float*)d_in[7];
    float* out = (float*)d_out;

    const int* src = ei;        // edge_index[0]
    const int* dst = ei + EE;   // edge_index[1]

    __half *p_hpre16, *p_h116, *p_h216;
    cudaGetSymbolAddress((void**)&p_hpre16, g_hpre16);
    cudaGetSymbolAddress((void**)&p_h116, g_h116);
    cudaGetSymbolAddress((void**)&p_h216, g_h216);

    const int NB_W = (NN * 32 + 255) / 256;   // warp-per-node grids

    count_kernel<<<NB_E, 256>>>(dst);                               // 1
    blocksum_kernel<<<NBLK, 512>>>();                               // 2
    rowptr_kernel<<<NBLK, 512>>>();                                 // 3
    gemm32_kernel<<<GFULL, 256>>>(x, W1, p_hpre16);                 // 4 (ncu target: first HMMA profile)
    fill_kernel<<<NB_E, 256>>>(src, dst);                           // 5
    agg_kernel<<<NB_W, 256>>>(p_hpre16, b1, p_h116);                // 6
    gemm16_kernel<<<GFULL, 256>>>(p_h116, W2, p_hpre16);            // 7
    agg_kernel<<<NB_W, 256>>>(p_hpre16, b2, p_h216);                // 8
    gemmout_kernel<<<GFULL, 256>>>(p_h116, p_h216, Wlin, blin, out);// 9
}